// round 5
// baseline (speedup 1.0000x reference)
#include <cuda_runtime.h>
#include <math.h>

// Scratch for r_inv (no cudaMalloc allowed).
__device__ float g_rinv[16384];

// ---------------------------------------------------------------------------
// Kernel 1: one 256-thread block per TWO rows. Threads 0-127 own row0,
// 128-255 own row1. Each thread loads 16 float4 in two front-batched groups
// of 8 (deep MLP), reduces via shuffle + tiny smem combine.
// 4096 blocks -> half the per-block reduce/launch overhead of R4.
// ---------------------------------------------------------------------------
__global__ void __launch_bounds__(256) rowsum_rinv_kernel(
    const float* __restrict__ adj, int n)
{
    const int tid   = threadIdx.x;
    const int half  = tid >> 7;            // 0 or 1: which row in the pair
    const int ht    = tid & 127;           // thread index within the half
    const int lane  = tid & 31;
    const int warp  = tid >> 5;            // 0..7
    const int row   = blockIdx.x * 2 + half;
    const int n4    = n >> 2;              // 2048
    if (row >= n) return;

    const float4* r4 = reinterpret_cast<const float4*>(adj + (size_t)row * n);

    // 2048 float4 / 128 threads = 16 each; two batches of 8 independent loads.
    float4 acc = make_float4(0.f, 0.f, 0.f, 0.f);
    #pragma unroll
    for (int b = 0; b < 2; ++b) {
        float4 v[8];
        #pragma unroll
        for (int k = 0; k < 8; ++k) {
            int c = ht + (b * 8 + k) * 128;
            v[k] = (c < n4) ? r4[c] : make_float4(0.f, 0.f, 0.f, 0.f);
        }
        #pragma unroll
        for (int k = 0; k < 8; ++k) {
            acc.x += v[k].x; acc.y += v[k].y; acc.z += v[k].z; acc.w += v[k].w;
        }
    }
    float s = (acc.x + acc.y) + (acc.z + acc.w);

    // warp reduce
    #pragma unroll
    for (int off = 16; off > 0; off >>= 1)
        s += __shfl_xor_sync(0xFFFFFFFFu, s, off);

    // 4 warps per row -> smem combine
    __shared__ float smem[8];
    if (lane == 0) smem[warp] = s;
    __syncthreads();
    if ((tid & 127) == 0) {                // one thread per row
        int w0 = half * 4;
        float t = smem[w0] + smem[w0 + 1] + smem[w0 + 2] + smem[w0 + 3];
        float rowsum = t + 1.0f;           // + I diagonal
        g_rinv[row] = (rowsum > 0.0f) ? rsqrtf(rowsum) : 0.0f;
    }
}

// ---------------------------------------------------------------------------
// Kernel 2: one block per row. out[i][j] = (adj[i][j] + (i==j)) * ri * rj
// At the mixed read+write DRAM ceiling (~78%); keep proven form.
// ---------------------------------------------------------------------------
__global__ void __launch_bounds__(256) scale_kernel(
    const float* __restrict__ adj, float* __restrict__ out, int n)
{
    const int row = blockIdx.x;
    const int tid = threadIdx.x;
    const float ri = g_rinv[row];
    const float4* arow = reinterpret_cast<const float4*>(adj + (size_t)row * n);
    float4* orow = reinterpret_cast<float4*>(out + (size_t)row * n);
    const float4* rinv4 = reinterpret_cast<const float4*>(g_rinv);
    const int n4 = n >> 2;                 // 2048

    #pragma unroll 8
    for (int c = tid; c < n4; c += 256) {
        float4 a = __ldcs(&arow[c]);
        float4 r = rinv4[c];               // hot 32KB vector, default caching
        int j0 = c << 2;
        a.x += (j0 + 0 == row) ? 1.0f : 0.0f;
        a.y += (j0 + 1 == row) ? 1.0f : 0.0f;
        a.z += (j0 + 2 == row) ? 1.0f : 0.0f;
        a.w += (j0 + 3 == row) ? 1.0f : 0.0f;
        float4 o;
        o.x = a.x * ri * r.x;
        o.y = a.y * ri * r.y;
        o.z = a.z * ri * r.z;
        o.w = a.w * ri * r.w;
        __stcs(&orow[c], o);
    }
}

extern "C" void kernel_launch(void* const* d_in, const int* in_sizes, int n_in,
                              void* d_out, int out_size)
{
    const float* adj = (const float*)d_in[0];
    float* out = (float*)d_out;

    int n = 1;
    {
        long long total = in_sizes[0];
        long long lo = 1, hi = 1 << 16;
        while (lo < hi) {
            long long mid = (lo + hi + 1) >> 1;
            if (mid * mid <= total) lo = mid; else hi = mid - 1;
        }
        n = (int)lo;
    }

    int blocks1 = (n + 1) / 2;
    rowsum_rinv_kernel<<<blocks1, 256>>>(adj, n);
    scale_kernel<<<n, 256>>>(adj, out, n);
}

// round 6
// speedup vs baseline: 1.0195x; 1.0195x over previous
#include <cuda_runtime.h>
#include <math.h>

// Scratch for r_inv (no cudaMalloc allowed).
__device__ float g_rinv[16384];

// ---------------------------------------------------------------------------
// Kernel 1: PERSISTENT block-per-row rowsum. grid = #resident blocks; each
// block strides rows (row += gridDim.x), so each block reads rows in ~7
// sequential passes and the temporally-LAST reads are the high-numbered rows
// (they stay L2-resident for kernel 2's reverse walk).
// Per row: 256 threads x 8 front-batched float4 loads, shuffle+smem reduce.
// ---------------------------------------------------------------------------
__global__ void __launch_bounds__(256) rowsum_rinv_kernel(
    const float* __restrict__ adj, int n)
{
    const int tid  = threadIdx.x;
    const int lane = tid & 31;
    const int warp = tid >> 5;
    const int n4   = n >> 2;               // 2048
    __shared__ float smem[8];

    for (int row = blockIdx.x; row < n; row += gridDim.x) {
        const float4* r4 = reinterpret_cast<const float4*>(adj + (size_t)row * n);

        float4 v[8];
        #pragma unroll
        for (int k = 0; k < 8; ++k) {
            int c = tid + k * 256;
            v[k] = (c < n4) ? r4[c] : make_float4(0.f, 0.f, 0.f, 0.f);
        }
        float4 acc = make_float4(0.f, 0.f, 0.f, 0.f);
        #pragma unroll
        for (int k = 0; k < 8; ++k) {
            acc.x += v[k].x; acc.y += v[k].y; acc.z += v[k].z; acc.w += v[k].w;
        }
        float s = (acc.x + acc.y) + (acc.z + acc.w);

        #pragma unroll
        for (int off = 16; off > 0; off >>= 1)
            s += __shfl_xor_sync(0xFFFFFFFFu, s, off);

        if (lane == 0) smem[warp] = s;
        __syncthreads();
        if (tid == 0) {
            float t = smem[0] + smem[1] + smem[2] + smem[3]
                    + smem[4] + smem[5] + smem[6] + smem[7];
            float rowsum = t + 1.0f;        // + I diagonal
            g_rinv[row] = (rowsum > 0.0f) ? rsqrtf(rowsum) : 0.0f;
        }
        __syncthreads();                    // protect smem for next row
    }
}

// ---------------------------------------------------------------------------
// Kernel 2: one block per row, REVERSE order -> first reads hit the rows
// kernel 1 touched last (still L2-resident). __ldcs: read-once evict-first
// (protects inherited lines). __stcs: streaming writes, never re-read.
// ---------------------------------------------------------------------------
__global__ void __launch_bounds__(256) scale_kernel(
    const float* __restrict__ adj, float* __restrict__ out, int n)
{
    const int row = (n - 1) - blockIdx.x;   // reverse order
    const int tid = threadIdx.x;
    const float ri = g_rinv[row];
    const float4* arow = reinterpret_cast<const float4*>(adj + (size_t)row * n);
    float4* orow = reinterpret_cast<float4*>(out + (size_t)row * n);
    const float4* rinv4 = reinterpret_cast<const float4*>(g_rinv);
    const int n4 = n >> 2;                  // 2048

    #pragma unroll 8
    for (int c = tid; c < n4; c += 256) {
        float4 a = __ldcs(&arow[c]);
        float4 r = rinv4[c];                // hot 32KB vector, default caching
        int j0 = c << 2;
        a.x += (j0 + 0 == row) ? 1.0f : 0.0f;
        a.y += (j0 + 1 == row) ? 1.0f : 0.0f;
        a.z += (j0 + 2 == row) ? 1.0f : 0.0f;
        a.w += (j0 + 3 == row) ? 1.0f : 0.0f;
        float4 o;
        o.x = a.x * ri * r.x;
        o.y = a.y * ri * r.y;
        o.z = a.z * ri * r.z;
        o.w = a.w * ri * r.w;
        __stcs(&orow[c], o);
    }
}

extern "C" void kernel_launch(void* const* d_in, const int* in_sizes, int n_in,
                              void* d_out, int out_size)
{
    const float* adj = (const float*)d_in[0];
    float* out = (float*)d_out;

    int n = 1;
    {
        long long total = in_sizes[0];
        long long lo = 1, hi = 1 << 16;
        while (lo < hi) {
            long long mid = (lo + hi + 1) >> 1;
            if (mid * mid <= total) lo = mid; else hi = mid - 1;
        }
        n = (int)lo;
    }

    // Persistent grid for kernel 1: all blocks resident.
    int dev = 0, sms = 0, occ = 0;
    cudaGetDevice(&dev);
    cudaDeviceGetAttribute(&sms, cudaDevAttrMultiProcessorCount, dev);
    cudaOccupancyMaxActiveBlocksPerMultiprocessor(&occ, rowsum_rinv_kernel, 256, 0);
    if (occ < 1) occ = 1;
    int grid1 = sms * occ;
    if (grid1 > n) grid1 = n;

    rowsum_rinv_kernel<<<grid1, 256>>>(adj, n);
    scale_kernel<<<n, 256>>>(adj, out, n);
}

// round 7
// speedup vs baseline: 1.0351x; 1.0153x over previous
#include <cuda_runtime.h>
#include <math.h>

// Scratch for r_inv (no cudaMalloc allowed).
__device__ float g_rinv[16384];

// ---------------------------------------------------------------------------
// Kernel 1: persistent block-per-row rowsum, SOFTWARE PIPELINED.
// Each loop step issues the NEXT row's 8 front-batched float4 loads before
// reducing the CURRENT row, so the shuffle/smem/barrier tail runs under the
// next row's DRAM latency. Two-buffer ping-pong, 2 blocks/SM (reg-limited).
// ---------------------------------------------------------------------------
__global__ void __launch_bounds__(256, 2) rowsum_rinv_kernel(
    const float* __restrict__ adj, int n)
{
    const int tid  = threadIdx.x;
    const int lane = tid & 31;
    const int warp = tid >> 5;
    const int g    = gridDim.x;
    __shared__ float smem[8];

    int row = blockIdx.x;
    if (row >= n) return;

    float4 v[8], w[8];

    // prologue: load first row
    {
        const float4* r4 = reinterpret_cast<const float4*>(adj + (size_t)row * n);
        #pragma unroll
        for (int k = 0; k < 8; ++k) v[k] = r4[tid + k * 256];
    }

    while (true) {
        // ---- issue loads for row+g into w, then reduce v (row) ----
        int nxt = row + g;
        if (nxt < n) {
            const float4* q4 = reinterpret_cast<const float4*>(adj + (size_t)nxt * n);
            #pragma unroll
            for (int k = 0; k < 8; ++k) w[k] = q4[tid + k * 256];
        }
        {
            float4 acc = make_float4(0.f, 0.f, 0.f, 0.f);
            #pragma unroll
            for (int k = 0; k < 8; ++k) {
                acc.x += v[k].x; acc.y += v[k].y; acc.z += v[k].z; acc.w += v[k].w;
            }
            float s = (acc.x + acc.y) + (acc.z + acc.w);
            #pragma unroll
            for (int off = 16; off > 0; off >>= 1)
                s += __shfl_xor_sync(0xFFFFFFFFu, s, off);
            if (lane == 0) smem[warp] = s;
            __syncthreads();
            if (tid == 0) {
                float t = smem[0] + smem[1] + smem[2] + smem[3]
                        + smem[4] + smem[5] + smem[6] + smem[7];
                float rs = t + 1.0f;
                g_rinv[row] = (rs > 0.f) ? rsqrtf(rs) : 0.f;
            }
            __syncthreads();
        }
        if (nxt >= n) break;
        row = nxt;

        // ---- issue loads for row+g into v, then reduce w (row) ----
        nxt = row + g;
        if (nxt < n) {
            const float4* q4 = reinterpret_cast<const float4*>(adj + (size_t)nxt * n);
            #pragma unroll
            for (int k = 0; k < 8; ++k) v[k] = q4[tid + k * 256];
        }
        {
            float4 acc = make_float4(0.f, 0.f, 0.f, 0.f);
            #pragma unroll
            for (int k = 0; k < 8; ++k) {
                acc.x += w[k].x; acc.y += w[k].y; acc.z += w[k].z; acc.w += w[k].w;
            }
            float s = (acc.x + acc.y) + (acc.z + acc.w);
            #pragma unroll
            for (int off = 16; off > 0; off >>= 1)
                s += __shfl_xor_sync(0xFFFFFFFFu, s, off);
            if (lane == 0) smem[warp] = s;
            __syncthreads();
            if (tid == 0) {
                float t = smem[0] + smem[1] + smem[2] + smem[3]
                        + smem[4] + smem[5] + smem[6] + smem[7];
                float rs = t + 1.0f;
                g_rinv[row] = (rs > 0.f) ? rsqrtf(rs) : 0.f;
            }
            __syncthreads();
        }
        if (nxt >= n) break;
        row = nxt;
    }
}

// ---------------------------------------------------------------------------
// Kernel 2: one block per row (at the mixed r+w DRAM ceiling; unchanged).
// ---------------------------------------------------------------------------
__global__ void __launch_bounds__(256) scale_kernel(
    const float* __restrict__ adj, float* __restrict__ out, int n)
{
    const int row = (n - 1) - blockIdx.x;
    const int tid = threadIdx.x;
    const float ri = g_rinv[row];
    const float4* arow = reinterpret_cast<const float4*>(adj + (size_t)row * n);
    float4* orow = reinterpret_cast<float4*>(out + (size_t)row * n);
    const float4* rinv4 = reinterpret_cast<const float4*>(g_rinv);
    const int n4 = n >> 2;

    #pragma unroll 8
    for (int c = tid; c < n4; c += 256) {
        float4 a = __ldcs(&arow[c]);
        float4 r = rinv4[c];
        int j0 = c << 2;
        a.x += (j0 + 0 == row) ? 1.0f : 0.0f;
        a.y += (j0 + 1 == row) ? 1.0f : 0.0f;
        a.z += (j0 + 2 == row) ? 1.0f : 0.0f;
        a.w += (j0 + 3 == row) ? 1.0f : 0.0f;
        float4 o;
        o.x = a.x * ri * r.x;
        o.y = a.y * ri * r.y;
        o.z = a.z * ri * r.z;
        o.w = a.w * ri * r.w;
        __stcs(&orow[c], o);
    }
}

extern "C" void kernel_launch(void* const* d_in, const int* in_sizes, int n_in,
                              void* d_out, int out_size)
{
    const float* adj = (const float*)d_in[0];
    float* out = (float*)d_out;

    int n = 1;
    {
        long long total = in_sizes[0];
        long long lo = 1, hi = 1 << 16;
        while (lo < hi) {
            long long mid = (lo + hi + 1) >> 1;
            if (mid * mid <= total) lo = mid; else hi = mid - 1;
        }
        n = (int)lo;
    }

    int dev = 0, sms = 0, occ = 0;
    cudaGetDevice(&dev);
    cudaDeviceGetAttribute(&sms, cudaDevAttrMultiProcessorCount, dev);
    cudaOccupancyMaxActiveBlocksPerMultiprocessor(&occ, rowsum_rinv_kernel, 256, 0);
    if (occ < 1) occ = 1;
    int grid1 = sms * occ;
    if (grid1 > n) grid1 = n;

    rowsum_rinv_kernel<<<grid1, 256>>>(adj, n);
    scale_kernel<<<n, 256>>>(adj, out, n);
}